// round 3
// baseline (speedup 1.0000x reference)
#include <cuda_runtime.h>
#include <math.h>
#include <stdint.h>

#define BATCH 25
#define SEQT  600
#define EMBD  300
#define HID   512
#define G3    1536              // 3*HID
#define MROWS (BATCH*SEQT)      // 15000

typedef unsigned long long u64;

// ---------------- scratch (device globals; no allocation allowed) ----------
__device__ float g_xg[(size_t)MROWS * G3];   // 92.16 MB, reused for xg0 then xg1
__device__ float g_out0[(size_t)MROWS * HID];// 30.72 MB  (layer-0 outputs, all t)
__device__ float g_hbuf0[BATCH * HID];
__device__ float g_hbuf1[BATCH * HID];
__device__ float g_h0f[BATCH * HID];
__device__ float g_h1f[BATCH * HID];
__device__ unsigned g_ctr;

// ---------------- packed f32x2 helpers (Blackwell FFMA2) --------------------
__device__ __forceinline__ u64 ffma2(u64 a, u64 b, u64 c) {
    u64 d;
    asm("fma.rn.f32x2 %0, %1, %2, %3;" : "=l"(d) : "l"(a), "l"(b), "l"(c));
    return d;
}
__device__ __forceinline__ u64 pack2(float x, float y) {
    u64 d;
    asm("mov.b64 %0, {%1, %2};" : "=l"(d) : "f"(x), "f"(y));
    return d;
}
__device__ __forceinline__ float2 unpack2(u64 v) {
    float2 r;
    asm("mov.b64 {%0, %1}, %2;" : "=f"(r.x), "=f"(r.y) : "l"(v));
    return r;
}

// ---------------- release/acquire grid-barrier primitives -------------------
__device__ __forceinline__ void red_release_add(unsigned* p, unsigned v) {
    asm volatile("red.release.gpu.global.add.u32 [%0], %1;"
                 :: "l"(p), "r"(v) : "memory");
}
__device__ __forceinline__ unsigned ld_acquire(unsigned* p) {
    unsigned v;
    asm volatile("ld.acquire.gpu.global.u32 %0, [%1];"
                 : "=r"(v) : "l"(p) : "memory");
    return v;
}

// ---------------- reset barrier counter (stream-ordered; no spinners alive)
__global__ void reset_kernel() {
    if (threadIdx.x == 0) g_ctr = 0u;
}

// ---------------- fp32 GEMM (double-buffered, FFMA2):
// g_xg[M x 1536] = A[M x K] @ W[1536 x K]^T + bias
// words != null  -> A row r = emb[words[r]] (embedding gather), K = 300
// words == null  -> A = g_out0, K = 512
__global__ __launch_bounds__(256) void gemm_kernel(
    const int*   __restrict__ words,
    const float* __restrict__ emb,
    const float* __restrict__ Wt,     // [1536][K]
    const float* __restrict__ bias,   // [1536]
    int K)
{
    __shared__ float As[2][8][132];
    __shared__ float Ws[2][8][132];

    const int tid  = threadIdx.x;
    const int tx   = tid & 15;
    const int ty   = tid >> 4;
    const int row0 = blockIdx.y * 128;
    const int col0 = blockIdx.x * 128;

    u64 acc2[8][4];
#pragma unroll
    for (int i = 0; i < 8; i++)
#pragma unroll
        for (int j = 0; j < 4; j++) acc2[i][j] = 0ull;

    const int lr  = tid >> 1;          // 0..127
    const int lkq = (tid & 1) * 4;     // 0 or 4
    const int grow = row0 + lr;

    const float* arow = nullptr;
    if (grow < MROWS)
        arow = words ? (emb + (size_t)words[grow] * K)
                     : (g_out0 + (size_t)grow * K);
    const float* wrow = Wt + (size_t)(col0 + lr) * K;

    const int nt = (K + 7) / 8;

    auto loadA = [&](int gk) -> float4 {
        float4 v = make_float4(0.f, 0.f, 0.f, 0.f);
        if (arow) {
            if (gk + 3 < K) v = *(const float4*)(arow + gk);
            else {
                if (gk + 0 < K) v.x = arow[gk + 0];
                if (gk + 1 < K) v.y = arow[gk + 1];
                if (gk + 2 < K) v.z = arow[gk + 2];
                if (gk + 3 < K) v.w = arow[gk + 3];
            }
        }
        return v;
    };
    auto loadW = [&](int gk) -> float4 {
        float4 v = make_float4(0.f, 0.f, 0.f, 0.f);
        if (gk + 3 < K) v = *(const float4*)(wrow + gk);
        else {
            if (gk + 0 < K) v.x = wrow[gk + 0];
            if (gk + 1 < K) v.y = wrow[gk + 1];
            if (gk + 2 < K) v.z = wrow[gk + 2];
            if (gk + 3 < K) v.w = wrow[gk + 3];
        }
        return v;
    };

    // prologue: tile 0 into buffer 0
    {
        float4 va = loadA(lkq);
        float4 vw = loadW(lkq);
        As[0][lkq + 0][lr] = va.x; As[0][lkq + 1][lr] = va.y;
        As[0][lkq + 2][lr] = va.z; As[0][lkq + 3][lr] = va.w;
        Ws[0][lkq + 0][lr] = vw.x; Ws[0][lkq + 1][lr] = vw.y;
        Ws[0][lkq + 2][lr] = vw.z; Ws[0][lkq + 3][lr] = vw.w;
    }
    __syncthreads();

    for (int it = 0; it < nt; it++) {
        const int buf  = it & 1;
        const int nbuf = buf ^ 1;
        const bool have = (it + 1) < nt;

        float4 va2, vw2;
        if (have) {
            va2 = loadA((it + 1) * 8 + lkq);
            vw2 = loadW((it + 1) * 8 + lkq);
        }

#pragma unroll
        for (int kk = 0; kk < 8; kk++) {
            float4 a0 = *(const float4*)&As[buf][kk][ty * 8];
            float4 a1 = *(const float4*)&As[buf][kk][ty * 8 + 4];
            // b pairs loaded directly as packed u64 (16B-aligned smem)
            ulonglong2 bp0 = *(const ulonglong2*)&Ws[buf][kk][tx * 8];
            ulonglong2 bp1 = *(const ulonglong2*)&Ws[buf][kk][tx * 8 + 4];
            u64 bp[4] = { bp0.x, bp0.y, bp1.x, bp1.y };
            u64 ad[8];
            ad[0] = pack2(a0.x, a0.x); ad[1] = pack2(a0.y, a0.y);
            ad[2] = pack2(a0.z, a0.z); ad[3] = pack2(a0.w, a0.w);
            ad[4] = pack2(a1.x, a1.x); ad[5] = pack2(a1.y, a1.y);
            ad[6] = pack2(a1.z, a1.z); ad[7] = pack2(a1.w, a1.w);
#pragma unroll
            for (int i = 0; i < 8; i++)
#pragma unroll
                for (int j = 0; j < 4; j++)
                    acc2[i][j] = ffma2(ad[i], bp[j], acc2[i][j]);
        }

        if (have) {
            As[nbuf][lkq + 0][lr] = va2.x; As[nbuf][lkq + 1][lr] = va2.y;
            As[nbuf][lkq + 2][lr] = va2.z; As[nbuf][lkq + 3][lr] = va2.w;
            Ws[nbuf][lkq + 0][lr] = vw2.x; Ws[nbuf][lkq + 1][lr] = vw2.y;
            Ws[nbuf][lkq + 2][lr] = vw2.z; Ws[nbuf][lkq + 3][lr] = vw2.w;
        }
        __syncthreads();
    }

#pragma unroll
    for (int i = 0; i < 8; i++) {
        const int gr = row0 + ty * 8 + i;
        if (gr >= MROWS) continue;
        float* crow = g_xg + (size_t)gr * G3 + col0 + tx * 8;
        const float* brow = bias + col0 + tx * 8;
#pragma unroll
        for (int j = 0; j < 4; j++) {
            float2 v = unpack2(acc2[i][j]);
            crow[j * 2 + 0] = v.x + brow[j * 2 + 0];
            crow[j * 2 + 1] = v.y + brow[j * 2 + 1];
        }
    }
}

// ---------------- persistent GRU layer: 128 blocks, 4 hidden units each -----
// Inner loop is pure FFMA2 on packed pairs; h staged transposed (pair-major)
// for conflict-free LDS.64; weights persist in smem as packed pairs.
__global__ __launch_bounds__(256, 1) void gru_layer_kernel(
    const float* __restrict__ w_hh,   // [1536][512]
    const float* __restrict__ b_hh,   // [1536]
    const float* __restrict__ h_init, // [25][512]
    int layer)
{
    extern __shared__ u64 smemu[];
    u64*   hs2 = smemu;                  // [256][25] packed h pairs (51.2 KB)
    u64*   ws2 = hs2 + 256 * 25;         // [12][258] packed w pairs  (24.8 KB)
    float* ps  = (float*)(ws2 + 12 * 258); // [8][12][32] warp partials (12.3 KB)
    float* bhs = ps + 8 * 12 * 32;       // [12]

    const int tid  = threadIdx.x;
    const int wid  = tid >> 5;
    const int lane = tid & 31;
    const int u0   = blockIdx.x * 4;
    const int kbeg = wid * 64;           // this warp's k-slice

    float* outp = (layer == 0) ? g_out0 : nullptr;
    float* hfin = (layer == 0) ? g_h0f : g_h1f;

    // load this block's 12 w_hh rows as packed pairs (row stride 258 u64)
    for (int i = tid; i < 12 * 128; i += blockDim.x) {
        const int j  = i >> 7;                 // local row 0..11
        const int kq = (i & 127) << 2;         // k 0..508 step 4
        const int grow = (j >> 2) * HID + u0 + (j & 3);
        float4 v = *(const float4*)(w_hh + (size_t)grow * HID + kq);
        ulonglong2 p;
        p.x = pack2(v.x, v.y);
        p.y = pack2(v.z, v.w);
        *(ulonglong2*)(ws2 + j * 258 + (kq >> 1)) = p;
    }
    if (tid < 12) bhs[tid] = b_hh[(tid >> 2) * HID + u0 + (tid & 3)];
    __syncthreads();

    // per-thread gate identity (tid < 100)
    const int gb = tid >> 2;          // batch 0..24
    const int gu = tid & 3;           // local unit
    const int u  = u0 + gu;

    for (int t = 0; t < SEQT; t++) {
        const float* hsrc = (t == 0) ? h_init : ((t & 1) ? g_hbuf0 : g_hbuf1);
        float*       wdst = (t & 1) ? g_hbuf1 : g_hbuf0;

        // --- prefetch xg[t] and h_old into registers (hidden under the GEMM)
        float xr = 0.f, xz = 0.f, xn = 0.f, hold = 0.f;
        if (tid < 100) {
            const float* xrow = g_xg + ((size_t)gb * SEQT + t) * G3;
            xr   = __ldcg(xrow + u);
            xz   = __ldcg(xrow + HID + u);
            xn   = __ldcg(xrow + 2 * HID + u);
            hold = __ldcg(hsrc + gb * HID + u);
        }

        // --- warp-local h staging (transposed pair-major): warp owns its slice
        {
            const float4* s4 = (const float4*)hsrc;      // [25][128] quads
            const int qbeg = kbeg >> 2;
#pragma unroll
            for (int i = lane; i < 400; i += 32) {       // 25 b x 16 quads
                const int b = i >> 4;
                const int q = i & 15;
                float4 v = __ldcg(s4 + b * 128 + qbeg + q);
                const int q2 = (kbeg >> 1) + 2 * q;
                hs2[(q2 + 0) * 25 + b] = pack2(v.x, v.y);
                hs2[(q2 + 1) * 25 + b] = pack2(v.z, v.w);
            }
        }
        __syncwarp();

        // --- gh partials over this warp's k-slice; lane <-> batch; pure FFMA2
        if (lane < BATCH) {
            u64 acc2[12];
#pragma unroll
            for (int j = 0; j < 12; j++) acc2[j] = 0ull;
#pragma unroll 4
            for (int kq = kbeg; kq < kbeg + 64; kq += 4) {
                const int q2 = kq >> 1;
                u64 ha = hs2[(q2 + 0) * 25 + lane];
                u64 hb = hs2[(q2 + 1) * 25 + lane];
#pragma unroll
                for (int j = 0; j < 12; j++) {
                    ulonglong2 w = *(const ulonglong2*)(ws2 + j * 258 + q2);
                    acc2[j] = ffma2(w.x, ha, acc2[j]);
                    acc2[j] = ffma2(w.y, hb, acc2[j]);
                }
            }
#pragma unroll
            for (int j = 0; j < 12; j++) {
                float2 s = unpack2(acc2[j]);
                ps[(wid * 12 + j) * 32 + lane] = s.x + s.y;
            }
        }
        __syncthreads();

        // --- reduce over 8 warps + gates + h update (100 threads)
        if (tid < 100) {
            float gr_ = bhs[gu], gz_ = bhs[4 + gu], gn_ = bhs[8 + gu];
#pragma unroll
            for (int w = 0; w < 8; w++) {
                gr_ += ps[(w * 12 + gu    ) * 32 + gb];
                gz_ += ps[(w * 12 + 4 + gu) * 32 + gb];
                gn_ += ps[(w * 12 + 8 + gu) * 32 + gb];
            }
            const float r = 1.f / (1.f + expf(-(xr + gr_)));
            const float z = 1.f / (1.f + expf(-(xz + gz_)));
            const float n = tanhf(xn + r * gn_);
            const float hn = (1.f - z) * n + z * hold;
            wdst[gb * HID + u] = hn;
            if (outp) outp[((size_t)gb * SEQT + t) * HID + u] = hn;
            if (t == SEQT - 1) hfin[gb * HID + u] = hn;
        }
        __syncthreads();

        // --- grid barrier (release arrive / acquire spin)
        if (t < SEQT - 1) {
            if (tid == 0) {
                red_release_add(&g_ctr, 1u);
                const unsigned target = (unsigned)(t + 1) * gridDim.x;
                while (ld_acquire(&g_ctr) < target) { }
            }
            __syncthreads();
        }
    }
}

// ---------------- finalize: sig = sigmoid(h1_final . fc_w + fc_b); pack out --
__global__ void finalize_kernel(const float* __restrict__ fc_w,
                                const float* __restrict__ fc_b,
                                float* __restrict__ out)
{
    if (blockIdx.x < 100) {
        const int idx = blockIdx.x * 256 + threadIdx.x;     // 0..25599
        const float v = (idx < BATCH * HID) ? g_h0f[idx]
                                            : g_h1f[idx - BATCH * HID];
        out[25 + idx] = v;
    } else {
        const int b = threadIdx.x;
        if (b < BATCH) {
            float s = fc_b[0];
            for (int k = 0; k < HID; k++)
                s += g_h1f[b * HID + k] * fc_w[k];
            out[b] = 1.f / (1.f + expf(-s));
        }
    }
}

// ---------------- launch ----------------------------------------------------
extern "C" void kernel_launch(void* const* d_in, const int* in_sizes, int n_in,
                              void* d_out, int out_size)
{
    const int*   words  = (const int*)  d_in[0];
    const float* hidden = (const float*)d_in[1];
    const float* emb    = (const float*)d_in[2];
    const float* w_ih0  = (const float*)d_in[3];
    const float* w_hh0  = (const float*)d_in[4];
    const float* b_ih0  = (const float*)d_in[5];
    const float* b_hh0  = (const float*)d_in[6];
    const float* w_ih1  = (const float*)d_in[7];
    const float* w_hh1  = (const float*)d_in[8];
    const float* b_ih1  = (const float*)d_in[9];
    const float* b_hh1  = (const float*)d_in[10];
    const float* fc_w   = (const float*)d_in[11];
    const float* fc_b   = (const float*)d_in[12];
    float* out = (float*)d_out;

    const size_t smem_bytes = (256 * 25 + 12 * 258) * sizeof(u64)
                            + (8 * 12 * 32 + 16) * sizeof(float);
    cudaFuncSetAttribute(gru_layer_kernel,
                         cudaFuncAttributeMaxDynamicSharedMemorySize,
                         (int)smem_bytes);

    const dim3 ggrid(G3 / 128, (MROWS + 127) / 128);

    // layer 0: xg0 (embedding gather fused), then recurrence (writes out0, h0f)
    gemm_kernel<<<ggrid, 256>>>(words, emb, w_ih0, b_ih0, EMBD);
    reset_kernel<<<1, 32>>>();
    gru_layer_kernel<<<128, 256, smem_bytes>>>(w_hh0, b_hh0, hidden, 0);

    // layer 1: xg1 from out0 (reuses g_xg), then recurrence (writes h1f)
    gemm_kernel<<<ggrid, 256>>>(nullptr, nullptr, w_ih1, b_ih1, HID);
    reset_kernel<<<1, 32>>>();
    gru_layer_kernel<<<128, 256, smem_bytes>>>(w_hh1, b_hh1, hidden + BATCH * HID, 1);

    finalize_kernel<<<101, 256>>>(fc_w, fc_b, out);
}

// round 4
// speedup vs baseline: 1.0746x; 1.0746x over previous
#include <cuda_runtime.h>
#include <math.h>
#include <stdint.h>

#define BATCH 25
#define SEQT  600
#define EMBD  300
#define HID   512
#define G3    1536              // 3*HID
#define MROWS (BATCH*SEQT)      // 15000

// ---------------- scratch (device globals; no allocation allowed) ----------
__device__ float g_xg[(size_t)MROWS * G3];   // xg0 only (layer-0 input gates)
__device__ float g_h0buf[2][BATCH * HID];
__device__ float g_h1buf[2][BATCH * HID];
__device__ float g_h0f[BATCH * HID];
__device__ float g_h1f[BATCH * HID];
__device__ unsigned g_ctr;

// ---------------- release/acquire grid-barrier primitives -------------------
__device__ __forceinline__ void red_release_add(unsigned* p, unsigned v) {
    asm volatile("red.release.gpu.global.add.u32 [%0], %1;"
                 :: "l"(p), "r"(v) : "memory");
}
__device__ __forceinline__ unsigned ld_acquire(unsigned* p) {
    unsigned v;
    asm volatile("ld.acquire.gpu.global.u32 %0, [%1];"
                 : "=r"(v) : "l"(p) : "memory");
    return v;
}

__global__ void reset_kernel() {
    if (threadIdx.x == 0) g_ctr = 0u;
}

// ---------------- fp32 GEMM (double-buffered), embedding gather fused:
// g_xg[M x 1536] = emb[words] @ w_ih0^T + b_ih0,  K = 300
__global__ __launch_bounds__(256) void gemm_kernel(
    const int*   __restrict__ words,
    const float* __restrict__ emb,
    const float* __restrict__ Wt,     // [1536][K]
    const float* __restrict__ bias,   // [1536]
    int K)
{
    __shared__ float As[2][8][132];
    __shared__ float Ws[2][8][132];

    const int tid  = threadIdx.x;
    const int tx   = tid & 15;
    const int ty   = tid >> 4;
    const int row0 = blockIdx.y * 128;
    const int col0 = blockIdx.x * 128;

    float acc[8][8];
#pragma unroll
    for (int i = 0; i < 8; i++)
#pragma unroll
        for (int j = 0; j < 8; j++) acc[i][j] = 0.f;

    const int lr  = tid >> 1;
    const int lkq = (tid & 1) * 4;
    const int grow = row0 + lr;

    const float* arow = nullptr;
    if (grow < MROWS) arow = emb + (size_t)words[grow] * K;
    const float* wrow = Wt + (size_t)(col0 + lr) * K;

    const int nt = (K + 7) / 8;

    auto loadA = [&](int gk) -> float4 {
        float4 v = make_float4(0.f, 0.f, 0.f, 0.f);
        if (arow) {
            if (gk + 3 < K) v = *(const float4*)(arow + gk);
            else {
                if (gk + 0 < K) v.x = arow[gk + 0];
                if (gk + 1 < K) v.y = arow[gk + 1];
                if (gk + 2 < K) v.z = arow[gk + 2];
                if (gk + 3 < K) v.w = arow[gk + 3];
            }
        }
        return v;
    };
    auto loadW = [&](int gk) -> float4 {
        float4 v = make_float4(0.f, 0.f, 0.f, 0.f);
        if (gk + 3 < K) v = *(const float4*)(wrow + gk);
        else {
            if (gk + 0 < K) v.x = wrow[gk + 0];
            if (gk + 1 < K) v.y = wrow[gk + 1];
            if (gk + 2 < K) v.z = wrow[gk + 2];
            if (gk + 3 < K) v.w = wrow[gk + 3];
        }
        return v;
    };

    {
        float4 va = loadA(lkq);
        float4 vw = loadW(lkq);
        As[0][lkq + 0][lr] = va.x; As[0][lkq + 1][lr] = va.y;
        As[0][lkq + 2][lr] = va.z; As[0][lkq + 3][lr] = va.w;
        Ws[0][lkq + 0][lr] = vw.x; Ws[0][lkq + 1][lr] = vw.y;
        Ws[0][lkq + 2][lr] = vw.z; Ws[0][lkq + 3][lr] = vw.w;
    }
    __syncthreads();

    for (int it = 0; it < nt; it++) {
        const int buf  = it & 1;
        const int nbuf = buf ^ 1;
        const bool have = (it + 1) < nt;

        float4 va2, vw2;
        if (have) {
            va2 = loadA((it + 1) * 8 + lkq);
            vw2 = loadW((it + 1) * 8 + lkq);
        }

#pragma unroll
        for (int kk = 0; kk < 8; kk++) {
            float a[8], b[8];
            float4 a0 = *(const float4*)&As[buf][kk][ty * 8];
            float4 a1 = *(const float4*)&As[buf][kk][ty * 8 + 4];
            float4 b0 = *(const float4*)&Ws[buf][kk][tx * 8];
            float4 b1 = *(const float4*)&Ws[buf][kk][tx * 8 + 4];
            a[0]=a0.x; a[1]=a0.y; a[2]=a0.z; a[3]=a0.w;
            a[4]=a1.x; a[5]=a1.y; a[6]=a1.z; a[7]=a1.w;
            b[0]=b0.x; b[1]=b0.y; b[2]=b0.z; b[3]=b0.w;
            b[4]=b1.x; b[5]=b1.y; b[6]=b1.z; b[7]=b1.w;
#pragma unroll
            for (int i = 0; i < 8; i++)
#pragma unroll
                for (int j = 0; j < 8; j++)
                    acc[i][j] = fmaf(a[i], b[j], acc[i][j]);
        }

        if (have) {
            As[nbuf][lkq + 0][lr] = va2.x; As[nbuf][lkq + 1][lr] = va2.y;
            As[nbuf][lkq + 2][lr] = va2.z; As[nbuf][lkq + 3][lr] = va2.w;
            Ws[nbuf][lkq + 0][lr] = vw2.x; Ws[nbuf][lkq + 1][lr] = vw2.y;
            Ws[nbuf][lkq + 2][lr] = vw2.z; Ws[nbuf][lkq + 3][lr] = vw2.w;
        }
        __syncthreads();
    }

#pragma unroll
    for (int i = 0; i < 8; i++) {
        const int gr = row0 + ty * 8 + i;
        if (gr >= MROWS) continue;
        float* crow = g_xg + (size_t)gr * G3 + col0 + tx * 8;
        const float* brow = bias + col0 + tx * 8;
#pragma unroll
        for (int j = 0; j < 8; j++)
            crow[j] = acc[i][j] + brow[j];
    }
}

// ---------------- fused two-layer GRU, pipeline-skewed, persistent ----------
// 128 blocks; block q owns units [4q,4q+4) of BOTH layers: 36 weight rows in
// smem (12 w_hh0 + 12 w_ih1 + 12 w_hh1). Super-step s:
//   A: gh0 = W_hh0 . h0[s-1]        -> layer0 step s      (s in [0,600))
//   B: gx1 = W_ih1 . h0[s-1]        -> xg1 for t=s-1
//   C: gh1 = W_hh1 . h1[s-2]        -> layer1 step s-1    (s in [1,601))
__global__ __launch_bounds__(256, 1) void gru_fused_kernel(
    const float* __restrict__ w_hh0, const float* __restrict__ b_hh0,
    const float* __restrict__ w_ih1, const float* __restrict__ b_ih1,
    const float* __restrict__ w_hh1, const float* __restrict__ b_hh1,
    const float* __restrict__ hinit)  // [2][25][512]
{
    extern __shared__ float sm[];
    float* hs0 = sm;                    // [25][516] staged h0[s-1]
    float* hs1 = hs0 + 25 * 516;        // [25][516] staged h1[s-2]
    float* ws  = hs1 + 25 * 516;        // [36][516] weight rows
    float* ps  = ws  + 36 * 516;        // [8][36][33] warp partials
    float* bs  = ps  + 8 * 36 * 33;     // [36] biases: bhh0 | bih1 | bhh1

    const int tid  = threadIdx.x;
    const int wid  = tid >> 5;
    const int lane = tid & 31;
    const int u0   = blockIdx.x * 4;
    const int kbeg = wid * 64;

    const float* hinit0 = hinit;
    const float* hinit1 = hinit + BATCH * HID;

    // ---- load 36 weight rows: j = m*12 + g*4 + uu
    {
        const float* mats[3] = { w_hh0, w_ih1, w_hh1 };
        for (int i = tid; i < 36 * 128; i += 256) {
            const int j  = i >> 7;
            const int kq = (i & 127) << 2;
            const int m  = j / 12;
            const int r  = j % 12;
            const int grow = (r >> 2) * HID + u0 + (r & 3);
            float4 v = *(const float4*)(mats[m] + (size_t)grow * HID + kq);
            float* dst = ws + j * 516 + kq;
            dst[0] = v.x; dst[1] = v.y; dst[2] = v.z; dst[3] = v.w;
        }
        if (tid < 36) {
            const int m = tid / 12, r = tid % 12;
            const float* bp = (m == 0) ? b_hh0 : (m == 1) ? b_ih1 : b_hh1;
            bs[tid] = bp[(r >> 2) * HID + u0 + (r & 3)];
        }
    }
    __syncthreads();

    for (int s = 0; s <= SEQT; s++) {
        const float* h0src = (s == 0) ? hinit0 : g_h0buf[(s - 1) & 1];
        const float* h1src = (s <= 1) ? hinit1 : g_h1buf[s & 1];
        float* h0dst = g_h0buf[s & 1];
        float* h1dst = g_h1buf[(s + 1) & 1];

        // ---- prefetch gate-phase operands (hidden under the GEMVs)
        float xr0 = 0.f, xz0 = 0.f, xn0 = 0.f, h0old = 0.f, h1old = 0.f;
        if (tid < 100 && s < SEQT) {
            const int gb = tid >> 2, gu = tid & 3, u = u0 + gu;
            const float* xrow = g_xg + ((size_t)gb * SEQT + s) * G3;
            xr0   = __ldcg(xrow + u);
            xz0   = __ldcg(xrow + HID + u);
            xn0   = __ldcg(xrow + 2 * HID + u);
            h0old = __ldcg(h0src + gb * HID + u);
        }
        if (tid >= 128 && tid < 228 && s >= 1) {
            const int tl = tid - 128;
            const int gb = tl >> 2, gu = tl & 3, u = u0 + gu;
            h1old = __ldcg(h1src + gb * HID + u);
        }

        // ---- warp-local staging of both h vectors (warp owns its k-slice)
        {
            const float4* s0 = (const float4*)h0src;   // [25][128] quads
            const float4* s1 = (const float4*)h1src;
            const int qbeg = kbeg >> 2;
            for (int i = lane; i < 400; i += 32) {
                const int b = i >> 4;
                const int q = i & 15;
                float4 v0 = __ldcg(s0 + b * 128 + qbeg + q);
                float4 v1 = __ldcg(s1 + b * 128 + qbeg + q);
                float* d0 = hs0 + b * 516 + kbeg + q * 4;
                float* d1 = hs1 + b * 516 + kbeg + q * 4;
                d0[0] = v0.x; d0[1] = v0.y; d0[2] = v0.z; d0[3] = v0.w;
                d1[0] = v1.x; d1[1] = v1.y; d1[2] = v1.z; d1[3] = v1.w;
            }
        }
        __syncwarp();

        // ---- 3 fused GEMVs over this warp's k-slice; lane <-> batch
        if (lane < BATCH) {
            float acc[36];
#pragma unroll
            for (int j = 0; j < 36; j++) acc[j] = 0.f;
            const float* h0r = hs0 + lane * 516;
            const float* h1r = hs1 + lane * 516;
#pragma unroll 2
            for (int kq = kbeg; kq < kbeg + 64; kq += 4) {
                float4 h0v = *(const float4*)(h0r + kq);
                float4 h1v = *(const float4*)(h1r + kq);
#pragma unroll
                for (int j = 0; j < 24; j++) {     // rows 0-11: hh0, 12-23: ih1
                    float4 wv = *(const float4*)(ws + j * 516 + kq);
                    acc[j] = fmaf(wv.x, h0v.x, acc[j]);
                    acc[j] = fmaf(wv.y, h0v.y, acc[j]);
                    acc[j] = fmaf(wv.z, h0v.z, acc[j]);
                    acc[j] = fmaf(wv.w, h0v.w, acc[j]);
                }
#pragma unroll
                for (int j = 24; j < 36; j++) {    // rows 24-35: hh1
                    float4 wv = *(const float4*)(ws + j * 516 + kq);
                    acc[j] = fmaf(wv.x, h1v.x, acc[j]);
                    acc[j] = fmaf(wv.y, h1v.y, acc[j]);
                    acc[j] = fmaf(wv.z, h1v.z, acc[j]);
                    acc[j] = fmaf(wv.w, h1v.w, acc[j]);
                }
            }
#pragma unroll
            for (int j = 0; j < 36; j++)
                ps[(wid * 36 + j) * 33 + lane] = acc[j];
        }
        __syncthreads();

        // ---- layer-0 gate update (threads 0..99)
        if (tid < 100 && s < SEQT) {
            const int gb = tid >> 2, gu = tid & 3, u = u0 + gu;
            float gr_ = bs[gu], gz_ = bs[4 + gu], gn_ = bs[8 + gu];
#pragma unroll
            for (int w = 0; w < 8; w++) {
                gr_ += ps[(w * 36 +      gu) * 33 + gb];
                gz_ += ps[(w * 36 +  4 + gu) * 33 + gb];
                gn_ += ps[(w * 36 +  8 + gu) * 33 + gb];
            }
            const float r = 1.f / (1.f + expf(-(xr0 + gr_)));
            const float z = 1.f / (1.f + expf(-(xz0 + gz_)));
            const float n = tanhf(xn0 + r * gn_);
            const float hn = (1.f - z) * n + z * h0old;
            h0dst[gb * HID + u] = hn;
            if (s == SEQT - 1) g_h0f[gb * HID + u] = hn;
        }

        // ---- layer-1 gate update (threads 128..227)
        if (tid >= 128 && tid < 228 && s >= 1) {
            const int tl = tid - 128;
            const int gb = tl >> 2, gu = tl & 3, u = u0 + gu;
            float xr = bs[12 + gu], xz = bs[16 + gu], xn = bs[20 + gu];
            float hr = bs[24 + gu], hz = bs[28 + gu], hn_ = bs[32 + gu];
#pragma unroll
            for (int w = 0; w < 8; w++) {
                xr  += ps[(w * 36 + 12 + gu) * 33 + gb];
                xz  += ps[(w * 36 + 16 + gu) * 33 + gb];
                xn  += ps[(w * 36 + 20 + gu) * 33 + gb];
                hr  += ps[(w * 36 + 24 + gu) * 33 + gb];
                hz  += ps[(w * 36 + 28 + gu) * 33 + gb];
                hn_ += ps[(w * 36 + 32 + gu) * 33 + gb];
            }
            const float r = 1.f / (1.f + expf(-(xr + hr)));
            const float z = 1.f / (1.f + expf(-(xz + hz)));
            const float n = tanhf(xn + r * hn_);
            const float hnew = (1.f - z) * n + z * h1old;
            h1dst[gb * HID + u] = hnew;
            if (s == SEQT) g_h1f[gb * HID + u] = hnew;
        }
        __syncthreads();

        // ---- grid barrier (release arrive / acquire spin)
        if (s < SEQT) {
            if (tid == 0) {
                red_release_add(&g_ctr, 1u);
                const unsigned target = (unsigned)(s + 1) * gridDim.x;
                while (ld_acquire(&g_ctr) < target) { }
            }
            __syncthreads();
        }
    }
}

// ---------------- finalize: sig = sigmoid(h1_final . fc_w + fc_b); pack out --
__global__ void finalize_kernel(const float* __restrict__ fc_w,
                                const float* __restrict__ fc_b,
                                float* __restrict__ out)
{
    if (blockIdx.x < 100) {
        const int idx = blockIdx.x * 256 + threadIdx.x;     // 0..25599
        const float v = (idx < BATCH * HID) ? g_h0f[idx]
                                            : g_h1f[idx - BATCH * HID];
        out[25 + idx] = v;
    } else {
        const int b = threadIdx.x;
        if (b < BATCH) {
            float s = fc_b[0];
            for (int k = 0; k < HID; k++)
                s += g_h1f[b * HID + k] * fc_w[k];
            out[b] = 1.f / (1.f + expf(-s));
        }
    }
}

// ---------------- launch ----------------------------------------------------
extern "C" void kernel_launch(void* const* d_in, const int* in_sizes, int n_in,
                              void* d_out, int out_size)
{
    const int*   words  = (const int*)  d_in[0];
    const float* hidden = (const float*)d_in[1];
    const float* emb    = (const float*)d_in[2];
    const float* w_ih0  = (const float*)d_in[3];
    const float* w_hh0  = (const float*)d_in[4];
    const float* b_ih0  = (const float*)d_in[5];
    const float* b_hh0  = (const float*)d_in[6];
    const float* w_ih1  = (const float*)d_in[7];
    const float* w_hh1  = (const float*)d_in[8];
    const float* b_ih1  = (const float*)d_in[9];
    const float* b_hh1  = (const float*)d_in[10];
    const float* fc_w   = (const float*)d_in[11];
    const float* fc_b   = (const float*)d_in[12];
    float* out = (float*)d_out;

    const size_t smem_bytes =
        (25 * 516 + 25 * 516 + 36 * 516 + 8 * 36 * 33 + 64) * sizeof(float);
    cudaFuncSetAttribute(gru_fused_kernel,
                         cudaFuncAttributeMaxDynamicSharedMemorySize,
                         (int)smem_bytes);

    const dim3 ggrid(G3 / 128, (MROWS + 127) / 128);

    // xg0 (embedding gather fused)
    gemm_kernel<<<ggrid, 256>>>(words, emb, w_ih0, b_ih0, EMBD);

    // fused two-layer recurrence (601 super-steps)
    reset_kernel<<<1, 32>>>();
    gru_fused_kernel<<<128, 256, smem_bytes>>>(
        w_hh0, b_hh0, w_ih1, b_ih1, w_hh1, b_hh1, hidden);

    finalize_kernel<<<101, 256>>>(fc_w, fc_b, out);
}

// round 5
// speedup vs baseline: 1.1245x; 1.0464x over previous
#include <cuda_runtime.h>
#include <math.h>
#include <stdint.h>

#define BATCH 25
#define SEQT  600
#define EMBD  300
#define HID   512
#define G3    1536              // 3*HID
#define MROWS (BATCH*SEQT)      // 15000

// ---------------- scratch (device globals; no allocation allowed) ----------
__device__ float g_xg[(size_t)MROWS * G3];   // xg0 only (layer-0 input gates)
__device__ float g_h0buf[2][BATCH * HID];
__device__ float g_h1buf[2][BATCH * HID];
__device__ float g_h0f[BATCH * HID];
__device__ float g_h1f[BATCH * HID];
__device__ unsigned g_ctr;

// ---------------- release/acquire grid-barrier primitives -------------------
__device__ __forceinline__ void red_release_add(unsigned* p, unsigned v) {
    asm volatile("red.release.gpu.global.add.u32 [%0], %1;"
                 :: "l"(p), "r"(v) : "memory");
}
__device__ __forceinline__ unsigned ld_acquire(unsigned* p) {
    unsigned v;
    asm volatile("ld.acquire.gpu.global.u32 %0, [%1];"
                 : "=r"(v) : "l"(p) : "memory");
    return v;
}

__global__ void reset_kernel() {
    if (threadIdx.x == 0) g_ctr = 0u;
}

// ---------------- fp32 GEMM (double-buffered), embedding gather fused:
// g_xg[M x 1536] = emb[words] @ w_ih0^T + b_ih0,  K = 300
__global__ __launch_bounds__(256) void gemm_kernel(
    const int*   __restrict__ words,
    const float* __restrict__ emb,
    const float* __restrict__ Wt,     // [1536][K]
    const float* __restrict__ bias,   // [1536]
    int K)
{
    __shared__ float As[2][8][132];
    __shared__ float Ws[2][8][132];

    const int tid  = threadIdx.x;
    const int tx   = tid & 15;
    const int ty   = tid >> 4;
    const int row0 = blockIdx.y * 128;
    const int col0 = blockIdx.x * 128;

    float acc[8][8];
#pragma unroll
    for (int i = 0; i < 8; i++)
#pragma unroll
        for (int j = 0; j < 8; j++) acc[i][j] = 0.f;

    const int lr  = tid >> 1;
    const int lkq = (tid & 1) * 4;
    const int grow = row0 + lr;

    const float* arow = nullptr;
    if (grow < MROWS) arow = emb + (size_t)words[grow] * K;
    const float* wrow = Wt + (size_t)(col0 + lr) * K;

    const int nt = (K + 7) / 8;

    auto loadA = [&](int gk) -> float4 {
        float4 v = make_float4(0.f, 0.f, 0.f, 0.f);
        if (arow) {
            if (gk + 3 < K) v = *(const float4*)(arow + gk);
            else {
                if (gk + 0 < K) v.x = arow[gk + 0];
                if (gk + 1 < K) v.y = arow[gk + 1];
                if (gk + 2 < K) v.z = arow[gk + 2];
                if (gk + 3 < K) v.w = arow[gk + 3];
            }
        }
        return v;
    };
    auto loadW = [&](int gk) -> float4 {
        float4 v = make_float4(0.f, 0.f, 0.f, 0.f);
        if (gk + 3 < K) v = *(const float4*)(wrow + gk);
        else {
            if (gk + 0 < K) v.x = wrow[gk + 0];
            if (gk + 1 < K) v.y = wrow[gk + 1];
            if (gk + 2 < K) v.z = wrow[gk + 2];
            if (gk + 3 < K) v.w = wrow[gk + 3];
        }
        return v;
    };

    {
        float4 va = loadA(lkq);
        float4 vw = loadW(lkq);
        As[0][lkq + 0][lr] = va.x; As[0][lkq + 1][lr] = va.y;
        As[0][lkq + 2][lr] = va.z; As[0][lkq + 3][lr] = va.w;
        Ws[0][lkq + 0][lr] = vw.x; Ws[0][lkq + 1][lr] = vw.y;
        Ws[0][lkq + 2][lr] = vw.z; Ws[0][lkq + 3][lr] = vw.w;
    }
    __syncthreads();

    for (int it = 0; it < nt; it++) {
        const int buf  = it & 1;
        const int nbuf = buf ^ 1;
        const bool have = (it + 1) < nt;

        float4 va2, vw2;
        if (have) {
            va2 = loadA((it + 1) * 8 + lkq);
            vw2 = loadW((it + 1) * 8 + lkq);
        }

#pragma unroll
        for (int kk = 0; kk < 8; kk++) {
            float a[8], b[8];
            float4 a0 = *(const float4*)&As[buf][kk][ty * 8];
            float4 a1 = *(const float4*)&As[buf][kk][ty * 8 + 4];
            float4 b0 = *(const float4*)&Ws[buf][kk][tx * 8];
            float4 b1 = *(const float4*)&Ws[buf][kk][tx * 8 + 4];
            a[0]=a0.x; a[1]=a0.y; a[2]=a0.z; a[3]=a0.w;
            a[4]=a1.x; a[5]=a1.y; a[6]=a1.z; a[7]=a1.w;
            b[0]=b0.x; b[1]=b0.y; b[2]=b0.z; b[3]=b0.w;
            b[4]=b1.x; b[5]=b1.y; b[6]=b1.z; b[7]=b1.w;
#pragma unroll
            for (int i = 0; i < 8; i++)
#pragma unroll
                for (int j = 0; j < 8; j++)
                    acc[i][j] = fmaf(a[i], b[j], acc[i][j]);
        }

        if (have) {
            As[nbuf][lkq + 0][lr] = va2.x; As[nbuf][lkq + 1][lr] = va2.y;
            As[nbuf][lkq + 2][lr] = va2.z; As[nbuf][lkq + 3][lr] = va2.w;
            Ws[nbuf][lkq + 0][lr] = vw2.x; Ws[nbuf][lkq + 1][lr] = vw2.y;
            Ws[nbuf][lkq + 2][lr] = vw2.z; Ws[nbuf][lkq + 3][lr] = vw2.w;
        }
        __syncthreads();
    }

#pragma unroll
    for (int i = 0; i < 8; i++) {
        const int gr = row0 + ty * 8 + i;
        if (gr >= MROWS) continue;
        float* crow = g_xg + (size_t)gr * G3 + col0 + tx * 8;
        const float* brow = bias + col0 + tx * 8;
#pragma unroll
        for (int j = 0; j < 8; j++)
            crow[j] = acc[i][j] + brow[j];
    }
}

// ---------------- fused two-layer GRU, barrier-hidden ih1 GEMV --------------
// 128 blocks; block q owns units [4q,4q+4) of both layers; 36 weight rows in
// smem: rows 0-11 = w_hh0, 12-23 = w_ih1, 24-35 = w_hh1.
// Step s (s = 0..601):
//   main phase : A = W_hh0·h0[s-1] (layer0 t=s), C = W_hh1·h1[s-3] (layer1
//                t=s-2). Gate updates write h0[s], h1[s-2].
//   window     : after barrier-arrive, B = W_ih1·h0[s-1] (gx1[s-1], consumed
//                at step s+1). Partials carried across the barrier in regs.
__global__ __launch_bounds__(256, 1) void gru_fused_kernel(
    const float* __restrict__ w_hh0, const float* __restrict__ b_hh0,
    const float* __restrict__ w_ih1, const float* __restrict__ b_ih1,
    const float* __restrict__ w_hh1, const float* __restrict__ b_hh1,
    const float* __restrict__ hinit)  // [2][25][512]
{
    extern __shared__ float sm[];
    float* hs0 = sm;                    // [25][516] staged h0[s-1]
    float* hs1 = hs0 + 25 * 516;        // [25][516] staged h1[s-3]
    float* ws  = hs1 + 25 * 516;        // [36][516] weight rows
    float* ps  = ws  + 36 * 516;        // [8][36][33] warp partials
    float* bs  = ps  + 8 * 36 * 33;     // [36] biases: bhh0 | bih1 | bhh1

    const int tid  = threadIdx.x;
    const int wid  = tid >> 5;
    const int lane = tid & 31;
    const int u0   = blockIdx.x * 4;
    const int kbeg = wid * 64;

    const float* hinit0 = hinit;
    const float* hinit1 = hinit + BATCH * HID;

    // ---- load 36 weight rows: j = m*12 + g*4 + uu
    {
        const float* mats[3] = { w_hh0, w_ih1, w_hh1 };
        for (int i = tid; i < 36 * 128; i += 256) {
            const int j  = i >> 7;
            const int kq = (i & 127) << 2;
            const int m  = j / 12;
            const int r  = j % 12;
            const int grow = (r >> 2) * HID + u0 + (r & 3);
            float4 v = *(const float4*)(mats[m] + (size_t)grow * HID + kq);
            float* dst = ws + j * 516 + kq;
            dst[0] = v.x; dst[1] = v.y; dst[2] = v.z; dst[3] = v.w;
        }
        if (tid < 36) {
            const int m = tid / 12, r = tid % 12;
            const float* bp = (m == 0) ? b_hh0 : (m == 1) ? b_ih1 : b_hh1;
            bs[tid] = bp[(r >> 2) * HID + u0 + (r & 3)];
        }
    }
    __syncthreads();

    float stashB[12];                    // gx1[s-1] partials (window output)
#pragma unroll
    for (int j = 0; j < 12; j++) stashB[j] = 0.f;

    for (int s = 0; s <= SEQT + 1; s++) {
        // h0[s-1]; h0[t] lives in g_h0buf[t&1]
        const float* h0src = (s == 0) ? hinit0 : g_h0buf[(s - 1) & 1];
        // h1[s-3]; h1[t] lives in g_h1buf[t&1]
        const float* h1src = (s <= 2) ? hinit1 : g_h1buf[(s + 1) & 1];
        float* h0dst = g_h0buf[s & 1];          // h0[s]
        float* h1dst = g_h1buf[s & 1];          // h1[s-2]

        // ---- prefetch gate-phase operands (hidden under the GEMVs)
        float xr0 = 0.f, xz0 = 0.f, xn0 = 0.f, h0old = 0.f, h1old = 0.f;
        if (tid < 100 && s < SEQT) {
            const int gb = tid >> 2, gu = tid & 3, u = u0 + gu;
            const float* xrow = g_xg + ((size_t)gb * SEQT + s) * G3;
            xr0   = __ldcg(xrow + u);
            xz0   = __ldcg(xrow + HID + u);
            xn0   = __ldcg(xrow + 2 * HID + u);
            h0old = __ldcg(h0src + gb * HID + u);
        }
        if (tid >= 128 && tid < 228 && s >= 2) {
            const int tl = tid - 128;
            const int gb = tl >> 2, gu = tl & 3, u = u0 + gu;
            h1old = __ldcg(h1src + gb * HID + u);
        }

        // ---- warp-local staging of h0[s-1] and h1[s-3] (warp owns k-slice)
        {
            const float4* s0 = (const float4*)h0src;   // [25][128] quads
            const float4* s1 = (const float4*)h1src;
            const int qbeg = kbeg >> 2;
            for (int i = lane; i < 400; i += 32) {
                const int b = i >> 4;
                const int q = i & 15;
                float4 v0 = __ldcg(s0 + b * 128 + qbeg + q);
                float4 v1 = __ldcg(s1 + b * 128 + qbeg + q);
                float* d0 = hs0 + b * 516 + kbeg + q * 4;
                float* d1 = hs1 + b * 516 + kbeg + q * 4;
                d0[0] = v0.x; d0[1] = v0.y; d0[2] = v0.z; d0[3] = v0.w;
                d1[0] = v1.x; d1[1] = v1.y; d1[2] = v1.z; d1[3] = v1.w;
            }
        }
        __syncwarp();

        // ---- main GEMVs A (rows 0-11, h0) + C (rows 24-35, h1); lane<->batch
        if (lane < BATCH) {
            float acc[24];
#pragma unroll
            for (int j = 0; j < 24; j++) acc[j] = 0.f;
            const float* h0r = hs0 + lane * 516;
            const float* h1r = hs1 + lane * 516;
#pragma unroll 2
            for (int kq = kbeg; kq < kbeg + 64; kq += 4) {
                float4 h0v = *(const float4*)(h0r + kq);
                float4 h1v = *(const float4*)(h1r + kq);
#pragma unroll
                for (int j = 0; j < 12; j++) {           // A: w_hh0 rows
                    float4 wv = *(const float4*)(ws + j * 516 + kq);
                    acc[j] = fmaf(wv.x, h0v.x, acc[j]);
                    acc[j] = fmaf(wv.y, h0v.y, acc[j]);
                    acc[j] = fmaf(wv.z, h0v.z, acc[j]);
                    acc[j] = fmaf(wv.w, h0v.w, acc[j]);
                }
#pragma unroll
                for (int j = 0; j < 12; j++) {           // C: w_hh1 rows
                    float4 wv = *(const float4*)(ws + (24 + j) * 516 + kq);
                    acc[12 + j] = fmaf(wv.x, h1v.x, acc[12 + j]);
                    acc[12 + j] = fmaf(wv.y, h1v.y, acc[12 + j]);
                    acc[12 + j] = fmaf(wv.z, h1v.z, acc[12 + j]);
                    acc[12 + j] = fmaf(wv.w, h1v.w, acc[12 + j]);
                }
            }
#pragma unroll
            for (int j = 0; j < 12; j++) {
                ps[(wid * 36 + j     ) * 33 + lane] = acc[j];       // A
                ps[(wid * 36 + 12 + j) * 33 + lane] = stashB[j];    // B (s-1)
                ps[(wid * 36 + 24 + j) * 33 + lane] = acc[12 + j];  // C
            }
        }
        __syncthreads();

        // ---- layer-0 gate update: t = s (threads 0..99)
        if (tid < 100 && s < SEQT) {
            const int gb = tid >> 2, gu = tid & 3, u = u0 + gu;
            float gr_ = bs[gu], gz_ = bs[4 + gu], gn_ = bs[8 + gu];
#pragma unroll
            for (int w = 0; w < 8; w++) {
                gr_ += ps[(w * 36 +      gu) * 33 + gb];
                gz_ += ps[(w * 36 +  4 + gu) * 33 + gb];
                gn_ += ps[(w * 36 +  8 + gu) * 33 + gb];
            }
            const float r = 1.f / (1.f + expf(-(xr0 + gr_)));
            const float z = 1.f / (1.f + expf(-(xz0 + gz_)));
            const float n = tanhf(xn0 + r * gn_);
            const float hn = (1.f - z) * n + z * h0old;
            h0dst[gb * HID + u] = hn;
            if (s == SEQT - 1) g_h0f[gb * HID + u] = hn;
        }

        // ---- layer-1 gate update: t = s-2 (threads 128..227)
        if (tid >= 128 && tid < 228 && s >= 2) {
            const int tl = tid - 128;
            const int gb = tl >> 2, gu = tl & 3, u = u0 + gu;
            float xr = bs[12 + gu], xz = bs[16 + gu], xn = bs[20 + gu];
            float hr = bs[24 + gu], hz = bs[28 + gu], hn_ = bs[32 + gu];
#pragma unroll
            for (int w = 0; w < 8; w++) {
                xr  += ps[(w * 36 + 12 + gu) * 33 + gb];
                xz  += ps[(w * 36 + 16 + gu) * 33 + gb];
                xn  += ps[(w * 36 + 20 + gu) * 33 + gb];
                hr  += ps[(w * 36 + 24 + gu) * 33 + gb];
                hz  += ps[(w * 36 + 28 + gu) * 33 + gb];
                hn_ += ps[(w * 36 + 32 + gu) * 33 + gb];
            }
            const float r = 1.f / (1.f + expf(-(xr + hr)));
            const float z = 1.f / (1.f + expf(-(xz + hz)));
            const float n = tanhf(xn + r * hn_);
            const float hnew = (1.f - z) * n + z * h1old;
            h1dst[gb * HID + u] = hnew;
            if (s == SEQT + 1) g_h1f[gb * HID + u] = hnew;
        }
        __syncthreads();   // all h stores done before arrive

        // ---- barrier arrive, then GEMV-B in the shadow of the barrier
        if (s < SEQT + 1) {
            if (tid == 0) red_release_add(&g_ctr, 1u);

            // B: gx1[s-1] = W_ih1 (rows 12-23) . h0[s-1]  (hs0 still valid)
            if (lane < BATCH) {
#pragma unroll
                for (int j = 0; j < 12; j++) stashB[j] = 0.f;
                const float* h0r = hs0 + lane * 516;
#pragma unroll 2
                for (int kq = kbeg; kq < kbeg + 64; kq += 4) {
                    float4 h0v = *(const float4*)(h0r + kq);
#pragma unroll
                    for (int j = 0; j < 12; j++) {
                        float4 wv = *(const float4*)(ws + (12 + j) * 516 + kq);
                        stashB[j] = fmaf(wv.x, h0v.x, stashB[j]);
                        stashB[j] = fmaf(wv.y, h0v.y, stashB[j]);
                        stashB[j] = fmaf(wv.z, h0v.z, stashB[j]);
                        stashB[j] = fmaf(wv.w, h0v.w, stashB[j]);
                    }
                }
            }

            if (tid == 0) {
                const unsigned target = (unsigned)(s + 1) * gridDim.x;
                while (ld_acquire(&g_ctr) < target) { }
            }
            __syncthreads();
        }
    }
}

// ---------------- finalize: sig = sigmoid(h1_final . fc_w + fc_b); pack out --
__global__ void finalize_kernel(const float* __restrict__ fc_w,
                                const float* __restrict__ fc_b,
                                float* __restrict__ out)
{
    if (blockIdx.x < 100) {
        const int idx = blockIdx.x * 256 + threadIdx.x;     // 0..25599
        const float v = (idx < BATCH * HID) ? g_h0f[idx]
                                            : g_h1f[idx - BATCH * HID];
        out[25 + idx] = v;
    } else {
        const int b = threadIdx.x;
        if (b < BATCH) {
            float s = fc_b[0];
            for (int k = 0; k < HID; k++)
                s += g_h1f[b * HID + k] * fc_w[k];
            out[b] = 1.f / (1.f + expf(-s));
        }
    }
}

// ---------------- launch ----------------------------------------------------
extern "C" void kernel_launch(void* const* d_in, const int* in_sizes, int n_in,
                              void* d_out, int out_size)
{
    const int*   words  = (const int*)  d_in[0];
    const float* hidden = (const float*)d_in[1];
    const float* emb    = (const float*)d_in[2];
    const float* w_ih0  = (const float*)d_in[3];
    const float* w_hh0  = (const float*)d_in[4];
    const float* b_ih0  = (const float*)d_in[5];
    const float* b_hh0  = (const float*)d_in[6];
    const float* w_ih1  = (const float*)d_in[7];
    const float* w_hh1  = (const float*)d_in[8];
    const float* b_ih1  = (const float*)d_in[9];
    const float* b_hh1  = (const float*)d_in[10];
    const float* fc_w   = (const float*)d_in[11];
    const float* fc_b   = (const float*)d_in[12];
    float* out = (float*)d_out;

    const size_t smem_bytes =
        (25 * 516 + 25 * 516 + 36 * 516 + 8 * 36 * 33 + 64) * sizeof(float);
    cudaFuncSetAttribute(gru_fused_kernel,
                         cudaFuncAttributeMaxDynamicSharedMemorySize,
                         (int)smem_bytes);

    const dim3 ggrid(G3 / 128, (MROWS + 127) / 128);

    // xg0 (embedding gather fused)
    gemm_kernel<<<ggrid, 256>>>(words, emb, w_ih0, b_ih0, EMBD);

    // fused two-layer recurrence (602 super-steps, barrier-hidden ih1 GEMV)
    reset_kernel<<<1, 32>>>();
    gru_fused_kernel<<<128, 256, smem_bytes>>>(
        w_hh0, b_hh0, w_ih1, b_ih1, w_hh1, b_hh1, hidden);

    finalize_kernel<<<101, 256>>>(fc_w, fc_b, out);
}